// round 3
// baseline (speedup 1.0000x reference)
#include <cuda_runtime.h>
#include <math.h>

// StatEncoder: bidirectional-GRU-ish encoder.
//   forward GRU over W=128 steps (only final h used)
//   backward GRU = single cell at h0=0 on x[:, -1, :]
//   head: GELU(concat @ Wp^T + bp) -> LayerNorm
//
// Round-1 baseline: fp32 SIMT, one launch per timestep (launch boundary
// provides the h(t) -> h(t+1) synchronization). Gate-transposed fused
// weight matrix Wt[k][gate*256+j] (k<256: Whh, k>=256: Wih) gives coalesced
// weight loads and folds the input projection into the same K loop.

#define Bsz  2048
#define Wlen 128
#define Fin  8
#define Hdim 256
#define G3   768          // 3*H
#define Kx   264          // 256 (h) + 8 (x)

// ---- scratch (static __device__: no runtime allocation) ----
__device__ float g_Wt[Kx * G3];            // [k][col], col = gate*256 + j   (~811 KB)
__device__ float g_Wpt[(2 * Hdim) * Hdim]; // transposed Wp: [m][j]          (512 KB)
__device__ float g_h[2][Bsz * Hdim];       // double-buffered hidden state   (4 MB)

// ---------------------------------------------------------------------------
// prep: build Wt, Wpt, zero h0. Idempotent; runs every launch (determinism).
// ---------------------------------------------------------------------------
__global__ void prep_kernel(const float* __restrict__ Whh_f,
                            const float* __restrict__ Wih_f,
                            const float* __restrict__ Wp) {
    int idx = blockIdx.x * blockDim.x + threadIdx.x;
    const int N1 = Kx * G3;            // 202752
    const int N2 = 2 * Hdim * Hdim;    // 131072
    const int N3 = Bsz * Hdim;         // 524288
    if (idx < N1) {
        int k = idx / G3, col = idx - k * G3;
        g_Wt[idx] = (k < Hdim) ? Whh_f[col * Hdim + k]
                               : Wih_f[col * Fin + (k - Hdim)];
    } else if (idx < N1 + N2) {
        int i = idx - N1;
        int m = i / Hdim, j = i - m * Hdim;
        g_Wpt[i] = Wp[j * (2 * Hdim) + m];
    } else if (idx < N1 + N2 + N3) {
        g_h[0][idx - N1 - N2] = 0.0f;
    }
}

// ---------------------------------------------------------------------------
// One GRU step. Grid (2, 64): blockIdx.x = j-tile (128 h-cols),
// blockIdx.y = batch tile (32 rows). 256 threads.
// Each thread: one j column, 16 batch rows, 4 accumulators per row.
// ---------------------------------------------------------------------------
__global__ __launch_bounds__(256, 2)
void gru_step_kernel(const float* __restrict__ x,
                     const float* __restrict__ bih,
                     const float* __restrict__ bhh,
                     int t, int inbuf) {
    __shared__ float hs[32][Kx];   // 32 rows x (256 h-cols + 8 x-cols)

    const int tx    = threadIdx.x;
    const int b0    = blockIdx.y * 32;
    const int j0    = blockIdx.x * 128 + (tx & 127);  // h column, 0..255
    const int rbase = (tx >> 7) * 16;                 // constant per warp

    const float* __restrict__ hin  = g_h[inbuf];
    float* __restrict__       hout = g_h[inbuf ^ 1];

    // load h tile (coalesced)
    for (int idx = tx; idx < 32 * Hdim; idx += 256) {
        int r = idx >> 8, k = idx & 255;
        hs[r][k] = hin[(b0 + r) * Hdim + k];
    }
    // load x(t) tile into the K-extension columns
    for (int idx = tx; idx < 32 * Fin; idx += 256) {
        int r = idx >> 3, c = idx & 7;
        hs[r][Hdim + c] = x[(b0 + r) * (Wlen * Fin) + t * Fin + c];
    }
    __syncthreads();

    float accr[16], accz[16], acchn[16], accinn[16];
#pragma unroll
    for (int i = 0; i < 16; i++) { accr[i] = 0.f; accz[i] = 0.f; acchn[i] = 0.f; accinn[i] = 0.f; }

    const float* __restrict__ WtR = g_Wt + j0;
    const float* __restrict__ WtZ = g_Wt + 256 + j0;
    const float* __restrict__ WtN = g_Wt + 512 + j0;

    // hidden part: k < 256 (n-gate contribution goes to acchn)
#pragma unroll 2
    for (int k = 0; k < Hdim; k++) {
        float wr = WtR[k * G3], wz = WtZ[k * G3], wn = WtN[k * G3];
#pragma unroll
        for (int i = 0; i < 16; i++) {
            float hv = hs[rbase + i][k];                 // warp broadcast
            accr[i]  = fmaf(hv, wr, accr[i]);
            accz[i]  = fmaf(hv, wz, accz[i]);
            acchn[i] = fmaf(hv, wn, acchn[i]);
        }
    }
    // input part: k in [256, 264) (n-gate contribution goes to accinn)
#pragma unroll
    for (int k = Hdim; k < Kx; k++) {
        float wr = WtR[k * G3], wz = WtZ[k * G3], wn = WtN[k * G3];
#pragma unroll
        for (int i = 0; i < 16; i++) {
            float hv = hs[rbase + i][k];
            accr[i]   = fmaf(hv, wr, accr[i]);
            accz[i]   = fmaf(hv, wz, accz[i]);
            accinn[i] = fmaf(hv, wn, accinn[i]);
        }
    }

    const float bir = bih[j0],       bhr = bhh[j0];
    const float biz = bih[256 + j0], bhz = bhh[256 + j0];
    const float bin = bih[512 + j0], bhn = bhh[512 + j0];

#pragma unroll
    for (int i = 0; i < 16; i++) {
        int   row = rbase + i;
        float ar = accr[i] + bir + bhr;
        float az = accz[i] + biz + bhz;
        float r  = 1.0f / (1.0f + __expf(-ar));
        float z  = 1.0f / (1.0f + __expf(-az));
        float an = (accinn[i] + bin) + r * (acchn[i] + bhn);
        an = fminf(fmaxf(an, -15.0f), 15.0f);   // tanh saturates; avoids inf/inf
        float e  = __expf(-2.0f * an);
        float n  = (1.0f - e) / (1.0f + e);
        float ho = hs[row][j0];
        hout[(b0 + row) * Hdim + j0] = (1.0f - z) * n + z * ho;
    }
}

// ---------------------------------------------------------------------------
// Head: h_bwd (closed form, h0=0) + projection + exact GELU + LayerNorm.
// One block per 8 batch rows, 256 threads.
// ---------------------------------------------------------------------------
__global__ __launch_bounds__(256)
void head_kernel(const float* __restrict__ x,
                 const float* __restrict__ Wih_b,
                 const float* __restrict__ bih_b,
                 const float* __restrict__ bhh_b,
                 const float* __restrict__ bp,
                 const float* __restrict__ gamma,
                 const float* __restrict__ beta,
                 float* __restrict__ out) {
    __shared__ float hf[8][Hdim];
    __shared__ float hb[8][Hdim];
    __shared__ float ys[8][Hdim];
    __shared__ float xs[8][Fin];

    const int tx = threadIdx.x;
    const int b0 = blockIdx.x * 8;
    const float* __restrict__ h0 = g_h[0];   // after 128 steps, final h is in buffer 0

    for (int idx = tx; idx < 8 * Hdim; idx += 256) {
        int r = idx >> 8, k = idx & 255;
        hf[r][k] = h0[(b0 + r) * Hdim + k];
    }
    if (tx < 64) {
        int r = tx >> 3, c = tx & 7;
        xs[r][c] = x[(b0 + r) * (Wlen * Fin) + (Wlen - 1) * Fin + c];
    }
    __syncthreads();

    // backward cell at h=0: gh = bhh_b, so h_bwd = (1-z)*n with
    // r = sig(gi_r + bhh_r), z = sig(gi_z + bhh_z), n = tanh(gi_n + r*bhh_n)
    {
        const int j = tx;
        float wr[Fin], wz[Fin], wn[Fin];
#pragma unroll
        for (int c = 0; c < Fin; c++) {
            wr[c] = Wih_b[j * Fin + c];
            wz[c] = Wih_b[(256 + j) * Fin + c];
            wn[c] = Wih_b[(512 + j) * Fin + c];
        }
        const float bir = bih_b[j],       bhr = bhh_b[j];
        const float biz = bih_b[256 + j], bhz = bhh_b[256 + j];
        const float bin = bih_b[512 + j], bhn = bhh_b[512 + j];
#pragma unroll
        for (int r8 = 0; r8 < 8; r8++) {
            float gr = bir + bhr, gz = biz + bhz, gn = bin;
#pragma unroll
            for (int c = 0; c < Fin; c++) {
                float xv = xs[r8][c];
                gr = fmaf(xv, wr[c], gr);
                gz = fmaf(xv, wz[c], gz);
                gn = fmaf(xv, wn[c], gn);
            }
            float r  = 1.0f / (1.0f + __expf(-gr));
            float z  = 1.0f / (1.0f + __expf(-gz));
            float an = gn + r * bhn;
            an = fminf(fmaxf(an, -15.0f), 15.0f);
            float e  = __expf(-2.0f * an);
            float n  = (1.0f - e) / (1.0f + e);
            hb[r8][j] = (1.0f - z) * n;
        }
    }
    __syncthreads();

    // y = GELU_exact( [hf|hb] @ Wp^T + bp )
    {
        const int j = tx;
#pragma unroll
        for (int r8 = 0; r8 < 8; r8++) {
            float acc = bp[j];
#pragma unroll 4
            for (int k = 0; k < Hdim; k++)
                acc = fmaf(hf[r8][k], g_Wpt[k * Hdim + j], acc);
#pragma unroll 4
            for (int k = 0; k < Hdim; k++)
                acc = fmaf(hb[r8][k], g_Wpt[(Hdim + k) * Hdim + j], acc);
            ys[r8][j] = 0.5f * acc * (1.0f + erff(acc * 0.70710678118654752f));
        }
    }
    __syncthreads();

    // LayerNorm: warp w handles row w
    const int w = tx >> 5, l = tx & 31;
    float s1 = 0.f, s2 = 0.f;
#pragma unroll
    for (int m = 0; m < 8; m++) {
        float v = ys[w][l + 32 * m];
        s1 += v; s2 += v * v;
    }
#pragma unroll
    for (int o = 16; o > 0; o >>= 1) {
        s1 += __shfl_xor_sync(0xffffffffu, s1, o);
        s2 += __shfl_xor_sync(0xffffffffu, s2, o);
    }
    const float mu  = s1 * (1.0f / 256.0f);
    const float var = s2 * (1.0f / 256.0f) - mu * mu;
    const float inv = rsqrtf(var + 1e-5f);
#pragma unroll
    for (int m = 0; m < 8; m++) {
        int col = l + 32 * m;
        float v = (ys[w][col] - mu) * inv;
        out[(b0 + w) * Hdim + col] = v * gamma[col] + beta[col];
    }
}

// ---------------------------------------------------------------------------
extern "C" void kernel_launch(void* const* d_in, const int* in_sizes, int n_in,
                              void* d_out, int out_size) {
    const float* x     = (const float*)d_in[0];
    const float* Wih_f = (const float*)d_in[1];
    const float* Whh_f = (const float*)d_in[2];
    const float* bih_f = (const float*)d_in[3];
    const float* bhh_f = (const float*)d_in[4];
    const float* Wih_b = (const float*)d_in[5];
    /* Whh_b = d_in[6] is mathematically unused (h0 = 0 backward cell) */
    const float* bih_b = (const float*)d_in[7];
    const float* bhh_b = (const float*)d_in[8];
    const float* Wp    = (const float*)d_in[9];
    const float* bp    = (const float*)d_in[10];
    const float* gamma = (const float*)d_in[11];
    const float* beta  = (const float*)d_in[12];
    float* out = (float*)d_out;

    const int totalPrep = Kx * G3 + 2 * Hdim * Hdim + Bsz * Hdim;
    prep_kernel<<<(totalPrep + 255) / 256, 256>>>(Whh_f, Wih_f, Wp);

    for (int t = 0; t < Wlen; t++) {
        gru_step_kernel<<<dim3(2, 64), 256>>>(x, bih_f, bhh_f, t, t & 1);
    }

    head_kernel<<<Bsz / 8, 256>>>(x, Wih_b, bih_b, bhh_b, bp, gamma, beta, out);
}

// round 5
// speedup vs baseline: 2.5112x; 2.5112x over previous
#include <cuda_runtime.h>
#include <cuda_bf16.h>
#include <math.h>

// StatEncoder — persistent mma.sync (bf16 HMMA) GRU for plain sm_100 target.
//   128 co-resident CTAs = 16 batch tiles x 8 column groups.
//   Per CTA/step: D[128,96] = A[128,256] @ W^T via m16n8k16 bf16 mma.sync,
//   A = hidden state in hi+lo bf16 split, stored in GLOBAL memory directly in
//   A-fragment layout (LDG.128 per fragment, no smem staging / ldmatrix).
//   Weights SMEM-resident in B-fragment layout (hi+lo). 3 passes: hi*Whi,
//   hi*Wlo, lo*Whi  => ~fp32 recurrence precision.
//   inn gate + all x-projections are exact fp32 SIMT (K=8, overlaps tensor).
//   Flag-array grid barrier between timesteps.

#define Bsz   2048
#define Wlen  128
#define Fin   8
#define Hdim  256
#define NCTA  128

#define N_WF   196608          // 8c x 2p x 16q x 12nf x 32L x 2w words
#define N_WX   6144            // 8c x 32jl x 3g x 8
#define N_HZ   524288          // parity-0 A buffers (both planes)
#define N_WPT  131072

// dynamic smem layout (bytes)
#define SMW_BYTES 98304        // 12288 words/plane x 2 planes x 4B
#define SM_WX     98304
#define SM_BIAS   101376
#define SM_TOTAL  105472

// ---- static device scratch ----
__device__ __align__(256) unsigned g_wfrag[N_WF];
__device__ __align__(256) float    g_wx[N_WX];
__device__ __align__(256) float    g_bias[1024];      // cb_r | cb_z | bhn | bin
__device__ __align__(256) unsigned g_hA[2 * 2 * 16 * 8 * 16 * 128]; // [par][pl][bt][mt][q][128w]
__device__ __align__(256) float    g_hfinal[Bsz * Hdim];
__device__ __align__(256) float    g_Wpt[N_WPT];
__device__ int g_flag[NCTA];

// ---- helpers ----
static __device__ __forceinline__ unsigned f2bf_bits(float f) {
    __nv_bfloat16 h = __float2bfloat16_rn(f);
    return (unsigned)reinterpret_cast<unsigned short&>(h);
}
static __device__ __forceinline__ float bfbits2f(unsigned u) {
    unsigned short us = (unsigned short)u;
    __nv_bfloat16 h = reinterpret_cast<__nv_bfloat16&>(us);
    return __bfloat162float(h);
}

#define MMA4(d, a, b0v, b1v)                                                   \
    asm volatile(                                                              \
        "mma.sync.aligned.m16n8k16.row.col.f32.bf16.bf16.f32 "                 \
        "{%0,%1,%2,%3}, {%4,%5,%6,%7}, {%8,%9}, {%0,%1,%2,%3};"                \
        : "+f"(d[0]), "+f"(d[1]), "+f"(d[2]), "+f"(d[3])                       \
        : "r"(a.x), "r"(a.y), "r"(a.z), "r"(a.w), "r"(b0v), "r"(b1v))

// ---------------- prep: pack weight fragments / wx / bias / zero state ------
#define N_PREP (N_WF + N_WX + 256 + N_HZ + NCTA + N_WPT)

__global__ void prep_kernel(const float* __restrict__ Whh_f,
                            const float* __restrict__ Wih_f,
                            const float* __restrict__ bih_f,
                            const float* __restrict__ bhh_f,
                            const float* __restrict__ Wp) {
    int idx = blockIdx.x * blockDim.x + threadIdx.x;
    if (idx < N_WF) {
        // B-fragment packing. word = bf16x2 (k, k+1).
        int c  = idx / 24576, r = idx % 24576;
        int p  = r / 12288,  r2 = r % 12288;
        int q  = r2 / 768,   r3 = r2 % 768;
        int nfg = r3 / 64,   r4 = r3 % 64;
        int L  = r4 >> 1,    ws = r4 & 1;
        int n  = nfg * 8 + (L >> 2);
        int wc = n / 48, r5 = n % 48;
        int gate = r5 / 16;                 // 0=r, 1=z, 2=hn
        int jl = wc * 16 + (r5 % 16);
        int j  = c * 32 + jl;
        int k0 = q * 16 + ((L & 3) << 1) + ws * 8;
        float v0 = Whh_f[(gate * 256 + j) * 256 + k0];
        float v1 = Whh_f[(gate * 256 + j) * 256 + k0 + 1];
        unsigned w0, w1;
        if (p == 0) { w0 = f2bf_bits(v0); w1 = f2bf_bits(v1); }
        else {
            unsigned h0 = f2bf_bits(v0), h1 = f2bf_bits(v1);
            w0 = f2bf_bits(v0 - bfbits2f(h0));
            w1 = f2bf_bits(v1 - bfbits2f(h1));
        }
        g_wfrag[idx] = w0 | (w1 << 16);
    } else if (idx < N_WF + N_WX) {
        int i = idx - N_WF;
        int c = i / 768, r = i % 768;
        int jl = r / 24, g = (r % 24) / 8, e = r % 8;
        int j = c * 32 + jl;
        g_wx[i] = Wih_f[(g * 256 + j) * 8 + e];    // g: 0=r, 1=z, 2=inn
    } else if (idx < N_WF + N_WX + 256) {
        int j = idx - N_WF - N_WX;
        g_bias[j]       = bih_f[j] + bhh_f[j];
        g_bias[256 + j] = bih_f[256 + j] + bhh_f[256 + j];
        g_bias[512 + j] = bhh_f[512 + j];
        g_bias[768 + j] = bih_f[512 + j];
    } else if (idx < N_WF + N_WX + 256 + N_HZ) {
        g_hA[idx - N_WF - N_WX - 256] = 0u;        // parity-0 buffers = h(0) = 0
    } else if (idx < N_WF + N_WX + 256 + N_HZ + NCTA) {
        g_flag[idx - N_WF - N_WX - 256 - N_HZ] = 0;
    } else if (idx < N_PREP) {
        int i = idx - N_WF - N_WX - 256 - N_HZ - NCTA;
        int m = i / Hdim, j = i - m * Hdim;
        g_Wpt[i] = Wp[j * (2 * Hdim) + m];
    }
}

// ---------------- persistent GRU -------------------------------------------
__global__ void __launch_bounds__(256, 1)
gru_persist(const float* __restrict__ x) {
    extern __shared__ unsigned smem[];
    const int tid = threadIdx.x;
    const int bt = blockIdx.x >> 3;     // batch tile 0..15
    const int c  = blockIdx.x & 7;      // column group 0..7

    // load resident weights / wx / bias
    {
        const uint4* src = (const uint4*)(g_wfrag + c * 24576);
        uint4* dst = (uint4*)smem;
        for (int i = tid; i < 24576 / 4; i += 256) dst[i] = src[i];
        float* wxd = (float*)((char*)smem + SM_WX);
        const float* wxs = g_wx + c * 768;
        for (int i = tid; i < 768; i += 256) wxd[i] = wxs[i];
        float* bd = (float*)((char*)smem + SM_BIAS);
        for (int i = tid; i < 1024; i += 256) bd[i] = g_bias[i];
    }
    __syncthreads();

    const int w  = tid >> 5, L = tid & 31;
    const int wr = w >> 1;              // M row-block (32 rows)
    const int wc = w & 1;               // N col half (16 jl)
    const unsigned* Wp0 = smem;                 // hi-plane frag words
    const unsigned* Wp1 = smem + 12288;         // lo-plane
    const float* swx = (const float*)((char*)smem + SM_WX);
    const float* sb  = (const float*)((char*)smem + SM_BIAS);

    float hold[16];
#pragma unroll
    for (int i = 0; i < 16; i++) hold[i] = 0.0f;

    const int qw = 2 * c + wc;          // the K-chunk this warp writes

    for (int t = 0; t < Wlen; t++) {
        const int par = t & 1;
        float acc[2][6][4];
#pragma unroll
        for (int m = 0; m < 2; m++)
#pragma unroll
            for (int nf = 0; nf < 6; nf++)
#pragma unroll
                for (int u = 0; u < 4; u++) acc[m][nf][u] = 0.0f;

        const unsigned* Ah0 = g_hA + (size_t)((((par * 2 + 0) * 16 + bt) * 8 + wr * 2 + 0) * 16) * 128;
        const unsigned* Ah1 = g_hA + (size_t)((((par * 2 + 0) * 16 + bt) * 8 + wr * 2 + 1) * 16) * 128;
        const unsigned* Al0 = g_hA + (size_t)((((par * 2 + 1) * 16 + bt) * 8 + wr * 2 + 0) * 16) * 128;
        const unsigned* Al1 = g_hA + (size_t)((((par * 2 + 1) * 16 + bt) * 8 + wr * 2 + 1) * 16) * 128;

#pragma unroll 4
        for (int q = 0; q < 16; q++) {
            uint4 fa0 = __ldcg((const uint4*)(Ah0 + q * 128) + L);
            uint4 fa1 = __ldcg((const uint4*)(Ah1 + q * 128) + L);
            uint4 fl0 = __ldcg((const uint4*)(Al0 + q * 128) + L);
            uint4 fl1 = __ldcg((const uint4*)(Al1 + q * 128) + L);
            unsigned bh[6][2];
            const int bbase = (q * 12 + wc * 6) * 64 + (L << 1);
#pragma unroll
            for (int nf = 0; nf < 6; nf++) {          // pass 1: A_hi * W_hi
                uint2 bb = *(const uint2*)(Wp0 + bbase + nf * 64);
                bh[nf][0] = bb.x; bh[nf][1] = bb.y;
                MMA4(acc[0][nf], fa0, bb.x, bb.y);
                MMA4(acc[1][nf], fa1, bb.x, bb.y);
            }
#pragma unroll
            for (int nf = 0; nf < 6; nf++) {          // pass 2: A_hi * W_lo
                uint2 bb = *(const uint2*)(Wp1 + bbase + nf * 64);
                MMA4(acc[0][nf], fa0, bb.x, bb.y);
                MMA4(acc[1][nf], fa1, bb.x, bb.y);
            }
#pragma unroll
            for (int nf = 0; nf < 6; nf++) {          // pass 3: A_lo * W_hi
                MMA4(acc[0][nf], fl0, bh[nf][0], bh[nf][1]);
                MMA4(acc[1][nf], fl1, bh[nf][0], bh[nf][1]);
            }
        }

        // ---- epilogue: x-projection (fp32) + gates + h update + frag store --
        const int pw = par ^ 1;
#pragma unroll
        for (int m = 0; m < 2; m++) {
            const int mt = wr * 2 + m;
#pragma unroll
            for (int rh = 0; rh < 2; rh++) {
                const int rmt = (L >> 2) + 8 * rh;            // row within mtile
                const int row = bt * 128 + mt * 16 + rmt;
                const float4 xv0 = __ldg((const float4*)(x + (size_t)row * (Wlen * Fin) + t * Fin));
                const float4 xv1 = __ldg((const float4*)(x + (size_t)row * (Wlen * Fin) + t * Fin) + 1);
                const float x8[8] = {xv0.x, xv0.y, xv0.z, xv0.w, xv1.x, xv1.y, xv1.z, xv1.w};
#pragma unroll
                for (int fp = 0; fp < 2; fp++) {
                    float hpair[2];
#pragma unroll
                    for (int e = 0; e < 2; e++) {
                        const int jl = wc * 16 + 2 * (L & 3) + 8 * fp + e;
                        const int j  = c * 32 + jl;
                        const float* wj = swx + jl * 24;
                        float xr = 0.f, xz = 0.f, xn = 0.f;
#pragma unroll
                        for (int u = 0; u < 8; u++) {
                            xr = fmaf(x8[u], wj[u], xr);
                            xz = fmaf(x8[u], wj[8 + u], xz);
                            xn = fmaf(x8[u], wj[16 + u], xn);
                        }
                        const int ci = rh * 2 + e;
                        float rp   = acc[m][fp][ci]     + xr + sb[j];
                        float zp   = acc[m][2 + fp][ci] + xz + sb[256 + j];
                        float hnv  = acc[m][4 + fp][ci] + sb[512 + j];
                        float innv = xn + sb[768 + j];
                        float r = __fdividef(1.0f, 1.0f + __expf(-rp));
                        float z = __fdividef(1.0f, 1.0f + __expf(-zp));
                        float an = innv + r * hnv;
                        an = fminf(fmaxf(an, -15.0f), 15.0f);
                        float e2 = __expf(-2.0f * an);
                        float n  = (1.0f - e2) * __fdividef(1.0f, 1.0f + e2);
                        const int hidx = ((m * 2 + rh) * 2 + fp) * 2 + e;
                        float h = (1.0f - z) * n + z * hold[hidx];
                        hold[hidx] = h;
                        hpair[e] = h;
                    }
                    // pack (j even, j odd) into one bf16x2 word, hi + lo planes
                    unsigned hb0 = f2bf_bits(hpair[0]);
                    unsigned hb1 = f2bf_bits(hpair[1]);
                    unsigned lb0 = f2bf_bits(hpair[0] - bfbits2f(hb0));
                    unsigned lb1 = f2bf_bits(hpair[1] - bfbits2f(hb1));
                    const int kp     = (L & 3) + 4 * fp;
                    const int lane_p = ((rmt & 7) << 2) + (kp & 3);
                    const int slot   = (rmt >> 3) + 2 * (kp >> 2);
                    unsigned* bhi = g_hA + (size_t)((((pw * 2 + 0) * 16 + bt) * 8 + mt) * 16 + qw) * 128;
                    unsigned* blo = g_hA + (size_t)((((pw * 2 + 1) * 16 + bt) * 8 + mt) * 16 + qw) * 128;
                    bhi[lane_p * 4 + slot] = hb0 | (hb1 << 16);
                    blo[lane_p * 4 + slot] = lb0 | (lb1 << 16);
                }
            }
        }

        // ---- grid barrier (flag array) ----
        __threadfence();
        __syncthreads();
        if (tid == 0) *((volatile int*)(g_flag + blockIdx.x)) = t + 1;
        if (tid < NCTA) {
            volatile int* f = (volatile int*)(g_flag + tid);
            long guard = 0;
            while (*f < t + 1 && guard < 1000000000L) guard++;
        }
        __threadfence();
        __syncthreads();
    }

    // final h -> plain layout for the head
#pragma unroll
    for (int m = 0; m < 2; m++)
#pragma unroll
        for (int rh = 0; rh < 2; rh++) {
            const int row = bt * 128 + (wr * 2 + m) * 16 + (L >> 2) + 8 * rh;
#pragma unroll
            for (int fp = 0; fp < 2; fp++)
#pragma unroll
                for (int e = 0; e < 2; e++) {
                    const int jl = wc * 16 + 2 * (L & 3) + 8 * fp + e;
                    const int hidx = ((m * 2 + rh) * 2 + fp) * 2 + e;
                    g_hfinal[(size_t)row * 256 + c * 32 + jl] = hold[hidx];
                }
        }
}

// ---------------- head: h_bwd + projection + GELU + LayerNorm ---------------
__global__ void __launch_bounds__(256)
head_kernel(const float* __restrict__ x,
            const float* __restrict__ Wih_b,
            const float* __restrict__ bih_b,
            const float* __restrict__ bhh_b,
            const float* __restrict__ bp,
            const float* __restrict__ gamma,
            const float* __restrict__ beta,
            float* __restrict__ out) {
    __shared__ float hf[8][Hdim];
    __shared__ float hb[8][Hdim];
    __shared__ float ys[8][Hdim];
    __shared__ float xs[8][Fin];

    const int tx = threadIdx.x;
    const int b0 = blockIdx.x * 8;

    for (int idx = tx; idx < 8 * Hdim; idx += 256) {
        int r = idx >> 8, k = idx & 255;
        hf[r][k] = g_hfinal[(size_t)(b0 + r) * Hdim + k];
    }
    if (tx < 64) {
        int r = tx >> 3, cc = tx & 7;
        xs[r][cc] = x[(size_t)(b0 + r) * (Wlen * Fin) + (Wlen - 1) * Fin + cc];
    }
    __syncthreads();

    {   // backward cell at h0 = 0
        const int j = tx;
        float wr[Fin], wz[Fin], wn[Fin];
#pragma unroll
        for (int cc = 0; cc < Fin; cc++) {
            wr[cc] = Wih_b[j * Fin + cc];
            wz[cc] = Wih_b[(256 + j) * Fin + cc];
            wn[cc] = Wih_b[(512 + j) * Fin + cc];
        }
        const float bir = bih_b[j],       bhr = bhh_b[j];
        const float biz = bih_b[256 + j], bhz = bhh_b[256 + j];
        const float bin = bih_b[512 + j], bhn = bhh_b[512 + j];
#pragma unroll
        for (int r8 = 0; r8 < 8; r8++) {
            float gr = bir + bhr, gz = biz + bhz, gn = bin;
#pragma unroll
            for (int cc = 0; cc < Fin; cc++) {
                float xv = xs[r8][cc];
                gr = fmaf(xv, wr[cc], gr);
                gz = fmaf(xv, wz[cc], gz);
                gn = fmaf(xv, wn[cc], gn);
            }
            float r = 1.0f / (1.0f + __expf(-gr));
            float z = 1.0f / (1.0f + __expf(-gz));
            float an = gn + r * bhn;
            an = fminf(fmaxf(an, -15.0f), 15.0f);
            float e = __expf(-2.0f * an);
            float n = (1.0f - e) / (1.0f + e);
            hb[r8][j] = (1.0f - z) * n;
        }
    }
    __syncthreads();

    {   // projection + exact GELU
        const int j = tx;
#pragma unroll
        for (int r8 = 0; r8 < 8; r8++) {
            float acc = bp[j];
#pragma unroll 4
            for (int k = 0; k < Hdim; k++)
                acc = fmaf(hf[r8][k], g_Wpt[k * Hdim + j], acc);
#pragma unroll 4
            for (int k = 0; k < Hdim; k++)
                acc = fmaf(hb[r8][k], g_Wpt[(Hdim + k) * Hdim + j], acc);
            ys[r8][j] = 0.5f * acc * (1.0f + erff(acc * 0.70710678118654752f));
        }
    }
    __syncthreads();

    const int w = tx >> 5, l = tx & 31;
    float s1 = 0.f, s2 = 0.f;
#pragma unroll
    for (int m = 0; m < 8; m++) {
        float v = ys[w][l + 32 * m];
        s1 += v; s2 += v * v;
    }
#pragma unroll
    for (int o = 16; o > 0; o >>= 1) {
        s1 += __shfl_xor_sync(0xffffffffu, s1, o);
        s2 += __shfl_xor_sync(0xffffffffu, s2, o);
    }
    const float mu  = s1 * (1.0f / 256.0f);
    const float var = s2 * (1.0f / 256.0f) - mu * mu;
    const float inv = rsqrtf(var + 1e-5f);
#pragma unroll
    for (int m = 0; m < 8; m++) {
        int col = l + 32 * m;
        float v = (ys[w][col] - mu) * inv;
        out[(size_t)(b0 + w) * Hdim + col] = v * gamma[col] + beta[col];
    }
}

// ---------------------------------------------------------------------------
extern "C" void kernel_launch(void* const* d_in, const int* in_sizes, int n_in,
                              void* d_out, int out_size) {
    const float* x     = (const float*)d_in[0];
    const float* Wih_f = (const float*)d_in[1];
    const float* Whh_f = (const float*)d_in[2];
    const float* bih_f = (const float*)d_in[3];
    const float* bhh_f = (const float*)d_in[4];
    const float* Wih_b = (const float*)d_in[5];
    /* Whh_b = d_in[6] unused: backward cell has h0 = 0 */
    const float* bih_b = (const float*)d_in[7];
    const float* bhh_b = (const float*)d_in[8];
    const float* Wp    = (const float*)d_in[9];
    const float* bp    = (const float*)d_in[10];
    const float* gamma = (const float*)d_in[11];
    const float* beta  = (const float*)d_in[12];
    float* out = (float*)d_out;

    cudaFuncSetAttribute(gru_persist, cudaFuncAttributeMaxDynamicSharedMemorySize, SM_TOTAL);

    prep_kernel<<<(N_PREP + 255) / 256, 256>>>(Whh_f, Wih_f, bih_f, bhh_f, Wp);
    gru_persist<<<NCTA, 256, SM_TOTAL>>>(x);
    head_kernel<<<Bsz / 8, 256>>>(x, Wih_b, bih_b, bhh_b, bp, gamma, beta, out);
}

// round 6
// speedup vs baseline: 3.2196x; 1.2821x over previous
#include <cuda_runtime.h>
#include <cuda_bf16.h>
#include <math.h>

// StatEncoder — persistent mma.sync (bf16 HMMA) GRU, plain sm_100 target.
//   Template MPW (mtiles-per-warp): MPW=1 -> 256 CTAs (M=64, 2 CTAs/SM,
//   4 warps/SMSP for cross-CTA overlap), MPW=2 -> 128 CTAs fallback (M=128).
//   Per CTA/step: D[M,96] = A[M,256] @ W^T, m16n8k16 bf16, 3 passes
//   (hi*Whi, hi*Wlo, lo*Whi) => ~fp32 recurrence precision.
//   Hidden state lives in GLOBAL memory directly in A-fragment layout,
//   addressed by global row-block rb = row>>4 (variant-independent).
//   Barrier is scoped to the 8 CTAs sharing a batch tile.

#define Bsz   2048
#define Wlen  128
#define Fin   8
#define Hdim  256

#define N_WF   196608          // 8c x 2p x 16q x 12nf x 32L x 2w words
#define N_WX   6144
#define N_HZ   524288          // parity-0 A planes
#define N_WPT  131072
#define NFLAG  256

// dynamic smem layout (bytes)
#define SM_WX     98304
#define SM_BIAS   101376
#define SM_TOTAL  105472

// ---- static device scratch ----
__device__ __align__(256) unsigned g_wfrag[N_WF];
__device__ __align__(256) float    g_wx[N_WX];
__device__ __align__(256) float    g_bias[1024];      // cb_r | cb_z | bhn | bin
// [par][pl][rb(128)][q(16)][128 words]
__device__ __align__(256) unsigned g_hA[2 * 2 * 128 * 16 * 128];
__device__ __align__(256) float    g_hfinal[Bsz * Hdim];
__device__ __align__(256) float    g_Wpt[N_WPT];
__device__ int g_flag[NFLAG];

// ---- helpers ----
static __device__ __forceinline__ unsigned f2bf_bits(float f) {
    __nv_bfloat16 h = __float2bfloat16_rn(f);
    return (unsigned)reinterpret_cast<unsigned short&>(h);
}
static __device__ __forceinline__ float bfbits2f(unsigned u) {
    unsigned short us = (unsigned short)u;
    __nv_bfloat16 h = reinterpret_cast<__nv_bfloat16&>(us);
    return __bfloat162float(h);
}

#define MMA4(d, a, b0v, b1v)                                                   \
    asm volatile(                                                              \
        "mma.sync.aligned.m16n8k16.row.col.f32.bf16.bf16.f32 "                 \
        "{%0,%1,%2,%3}, {%4,%5,%6,%7}, {%8,%9}, {%0,%1,%2,%3};"                \
        : "+f"(d[0]), "+f"(d[1]), "+f"(d[2]), "+f"(d[3])                       \
        : "r"(a.x), "r"(a.y), "r"(a.z), "r"(a.w), "r"(b0v), "r"(b1v))

// ---------------- prep ------------------------------------------------------
#define N_PREP (N_WF + N_WX + 256 + N_HZ + NFLAG + N_WPT)

__global__ void prep_kernel(const float* __restrict__ Whh_f,
                            const float* __restrict__ Wih_f,
                            const float* __restrict__ bih_f,
                            const float* __restrict__ bhh_f,
                            const float* __restrict__ Wp) {
    int idx = blockIdx.x * blockDim.x + threadIdx.x;
    if (idx < N_WF) {
        int c  = idx / 24576, r = idx % 24576;
        int p  = r / 12288,  r2 = r % 12288;
        int q  = r2 / 768,   r3 = r2 % 768;
        int nfg = r3 / 64,   r4 = r3 % 64;
        int L  = r4 >> 1,    ws = r4 & 1;
        int n  = nfg * 8 + (L >> 2);
        int wc = n / 48, r5 = n % 48;
        int gate = r5 / 16;                 // 0=r, 1=z, 2=hn
        int jl = wc * 16 + (r5 % 16);
        int j  = c * 32 + jl;
        int k0 = q * 16 + ((L & 3) << 1) + ws * 8;
        float v0 = Whh_f[(gate * 256 + j) * 256 + k0];
        float v1 = Whh_f[(gate * 256 + j) * 256 + k0 + 1];
        unsigned w0, w1;
        if (p == 0) { w0 = f2bf_bits(v0); w1 = f2bf_bits(v1); }
        else {
            unsigned h0 = f2bf_bits(v0), h1 = f2bf_bits(v1);
            w0 = f2bf_bits(v0 - bfbits2f(h0));
            w1 = f2bf_bits(v1 - bfbits2f(h1));
        }
        g_wfrag[idx] = w0 | (w1 << 16);
    } else if (idx < N_WF + N_WX) {
        int i = idx - N_WF;
        int c = i / 768, r = i % 768;
        int jl = r / 24, g = (r % 24) / 8, e = r % 8;
        int j = c * 32 + jl;
        g_wx[i] = Wih_f[(g * 256 + j) * 8 + e];    // g: 0=r, 1=z, 2=inn
    } else if (idx < N_WF + N_WX + 256) {
        int j = idx - N_WF - N_WX;
        g_bias[j]       = bih_f[j] + bhh_f[j];
        g_bias[256 + j] = bih_f[256 + j] + bhh_f[256 + j];
        g_bias[512 + j] = bhh_f[512 + j];
        g_bias[768 + j] = bih_f[512 + j];
    } else if (idx < N_WF + N_WX + 256 + N_HZ) {
        g_hA[idx - N_WF - N_WX - 256] = 0u;        // parity-0 planes = h(0) = 0
    } else if (idx < N_WF + N_WX + 256 + N_HZ + NFLAG) {
        g_flag[idx - N_WF - N_WX - 256 - N_HZ] = 0;
    } else if (idx < N_PREP) {
        int i = idx - N_WF - N_WX - 256 - N_HZ - NFLAG;
        int m = i / Hdim, j = i - m * Hdim;
        g_Wpt[i] = Wp[j * (2 * Hdim) + m];
    }
}

// ---------------- persistent GRU -------------------------------------------
template<int MPW>
__global__ void __launch_bounds__(256, 2)
gru_persist(const float* __restrict__ x) {
    extern __shared__ unsigned smem[];
    const int tid = threadIdx.x;
    const int bt = blockIdx.x >> 3;     // batch-tile group
    const int c  = blockIdx.x & 7;      // column group 0..7

    // resident weights / wx / bias
    {
        const uint4* src = (const uint4*)(g_wfrag + c * 24576);
        uint4* dst = (uint4*)smem;
        for (int i = tid; i < 6144; i += 256) dst[i] = src[i];
        float* wxd = (float*)((char*)smem + SM_WX);
        const float* wxs = g_wx + c * 768;
        for (int i = tid; i < 768; i += 256) wxd[i] = wxs[i];
        float* bd = (float*)((char*)smem + SM_BIAS);
        for (int i = tid; i < 1024; i += 256) bd[i] = g_bias[i];
    }
    __syncthreads();

    const int w  = tid >> 5, L = tid & 31;
    const int wr = w >> 1;              // warp row-group
    const int wc = w & 1;               // N col half (16 jl)
    const unsigned* Wp0 = smem;                 // hi-plane B frags
    const unsigned* Wp1 = smem + 12288;         // lo-plane
    const float* swx = (const float*)((char*)smem + SM_WX);
    const float* sb  = (const float*)((char*)smem + SM_BIAS);
    const int qw  = 2 * c + wc;         // K-chunk this warp produces
    const int rbw = bt * (4 * MPW) + wr * MPW;  // first global row-block

    float hold[MPW * 8];
#pragma unroll
    for (int i = 0; i < MPW * 8; i++) hold[i] = 0.0f;

    for (int t = 0; t < Wlen; t++) {
        const int par = t & 1;
        float acc[MPW][6][4];
#pragma unroll
        for (int m = 0; m < MPW; m++)
#pragma unroll
            for (int nf = 0; nf < 6; nf++)
#pragma unroll
                for (int u = 0; u < 4; u++) acc[m][nf][u] = 0.0f;

        // x(t) prefetch (independent of h, hides under the K loop)
        float4 xv[MPW * 2][2];
#pragma unroll
        for (int m = 0; m < MPW; m++)
#pragma unroll
            for (int rh = 0; rh < 2; rh++) {
                const int row = (rbw + m) * 16 + (L >> 2) + 8 * rh;
                const float4* xp = (const float4*)(x + (size_t)row * (Wlen * Fin) + t * Fin);
                xv[m * 2 + rh][0] = __ldg(xp);
                xv[m * 2 + rh][1] = __ldg(xp + 1);
            }

        const unsigned* Ah = g_hA + ((size_t)(par * 2 + 0) * 128 + rbw) * 2048;
        const unsigned* Al = g_hA + ((size_t)(par * 2 + 1) * 128 + rbw) * 2048;

#pragma unroll 4
        for (int q = 0; q < 16; q++) {
            uint4 fa[MPW], fl[MPW];
#pragma unroll
            for (int m = 0; m < MPW; m++) {
                fa[m] = __ldcg((const uint4*)(Ah + (size_t)m * 2048 + q * 128) + L);
                fl[m] = __ldcg((const uint4*)(Al + (size_t)m * 2048 + q * 128) + L);
            }
            unsigned bh[6][2];
            const int bbase = (q * 12 + wc * 6) * 64 + (L << 1);
#pragma unroll
            for (int nf = 0; nf < 6; nf++) {          // pass 1: A_hi * W_hi
                uint2 bb = *(const uint2*)(Wp0 + bbase + nf * 64);
                bh[nf][0] = bb.x; bh[nf][1] = bb.y;
#pragma unroll
                for (int m = 0; m < MPW; m++) MMA4(acc[m][nf], fa[m], bb.x, bb.y);
            }
#pragma unroll
            for (int nf = 0; nf < 6; nf++) {          // pass 2: A_hi * W_lo
                uint2 bb = *(const uint2*)(Wp1 + bbase + nf * 64);
#pragma unroll
                for (int m = 0; m < MPW; m++) MMA4(acc[m][nf], fa[m], bb.x, bb.y);
            }
#pragma unroll
            for (int nf = 0; nf < 6; nf++)            // pass 3: A_lo * W_hi
#pragma unroll
                for (int m = 0; m < MPW; m++) MMA4(acc[m][nf], fl[m], bh[nf][0], bh[nf][1]);
        }

        // ---- epilogue: x-proj (fp32) + gates + h update + frag store -------
        const int pw = par ^ 1;
#pragma unroll
        for (int m = 0; m < MPW; m++) {
            const int rb = rbw + m;
#pragma unroll
            for (int rh = 0; rh < 2; rh++) {
                const int rmt = (L >> 2) + 8 * rh;
                const float x8[8] = {xv[m * 2 + rh][0].x, xv[m * 2 + rh][0].y,
                                     xv[m * 2 + rh][0].z, xv[m * 2 + rh][0].w,
                                     xv[m * 2 + rh][1].x, xv[m * 2 + rh][1].y,
                                     xv[m * 2 + rh][1].z, xv[m * 2 + rh][1].w};
#pragma unroll
                for (int fp = 0; fp < 2; fp++) {
                    float hpair[2];
#pragma unroll
                    for (int e = 0; e < 2; e++) {
                        const int jl = wc * 16 + 2 * (L & 3) + 8 * fp + e;
                        const int j  = c * 32 + jl;
                        const float* wj = swx + jl * 24;
                        float xr = 0.f, xz = 0.f, xn = 0.f;
#pragma unroll
                        for (int u = 0; u < 8; u++) {
                            xr = fmaf(x8[u], wj[u], xr);
                            xz = fmaf(x8[u], wj[8 + u], xz);
                            xn = fmaf(x8[u], wj[16 + u], xn);
                        }
                        const int ci = rh * 2 + e;
                        float rp   = acc[m][fp][ci]     + xr + sb[j];
                        float zp   = acc[m][2 + fp][ci] + xz + sb[256 + j];
                        float hnv  = acc[m][4 + fp][ci] + sb[512 + j];
                        float innv = xn + sb[768 + j];
                        float r = __fdividef(1.0f, 1.0f + __expf(-rp));
                        float z = __fdividef(1.0f, 1.0f + __expf(-zp));
                        float an = innv + r * hnv;
                        an = fminf(fmaxf(an, -15.0f), 15.0f);
                        float e2 = __expf(-2.0f * an);
                        float n  = (1.0f - e2) * __fdividef(1.0f, 1.0f + e2);
                        const int hidx = ((m * 2 + rh) * 2 + fp) * 2 + e;
                        float h = (1.0f - z) * n + z * hold[hidx];
                        hold[hidx] = h;
                        hpair[e] = h;
                    }
                    unsigned hb0 = f2bf_bits(hpair[0]);
                    unsigned hb1 = f2bf_bits(hpair[1]);
                    unsigned lb0 = f2bf_bits(hpair[0] - bfbits2f(hb0));
                    unsigned lb1 = f2bf_bits(hpair[1] - bfbits2f(hb1));
                    const int kp     = (L & 3) + 4 * fp;
                    const int lane_p = ((rmt & 7) << 2) + (kp & 3);
                    const int slot   = (rmt >> 3) + 2 * (kp >> 2);
                    unsigned* bhi = g_hA + ((size_t)(pw * 2 + 0) * 128 + rb) * 2048 + qw * 128;
                    unsigned* blo = g_hA + ((size_t)(pw * 2 + 1) * 128 + rb) * 2048 + qw * 128;
                    bhi[lane_p * 4 + slot] = hb0 | (hb1 << 16);
                    blo[lane_p * 4 + slot] = lb0 | (lb1 << 16);
                }
            }
        }

        // ---- 8-CTA group barrier (release/acquire via flags) --------------
        __syncthreads();
        if (tid == 0) {
            __threadfence();           // release: orders ALL threads' STGs (via bar) before flag
            ((volatile int*)g_flag)[blockIdx.x] = t + 1;
        }
        if (tid < 8) {
            volatile int* f = (volatile int*)(g_flag + bt * 8 + tid);
            long guard = 0;
            while (*f < t + 1 && guard < 1000000000L) guard++;
            __threadfence();           // acquire
        }
        __syncthreads();
    }

    // final h -> plain layout for the head
#pragma unroll
    for (int m = 0; m < MPW; m++)
#pragma unroll
        for (int rh = 0; rh < 2; rh++) {
            const int row = (rbw + m) * 16 + (L >> 2) + 8 * rh;
#pragma unroll
            for (int fp = 0; fp < 2; fp++)
#pragma unroll
                for (int e = 0; e < 2; e++) {
                    const int jl = wc * 16 + 2 * (L & 3) + 8 * fp + e;
                    const int hidx = ((m * 2 + rh) * 2 + fp) * 2 + e;
                    g_hfinal[(size_t)row * 256 + c * 32 + jl] = hold[hidx];
                }
        }
}

// ---------------- head: h_bwd + projection + GELU + LayerNorm ---------------
__global__ void __launch_bounds__(256)
head_kernel(const float* __restrict__ x,
            const float* __restrict__ Wih_b,
            const float* __restrict__ bih_b,
            const float* __restrict__ bhh_b,
            const float* __restrict__ bp,
            const float* __restrict__ gamma,
            const float* __restrict__ beta,
            float* __restrict__ out) {
    __shared__ float hf[8][Hdim];
    __shared__ float hb[8][Hdim];
    __shared__ float ys[8][Hdim];
    __shared__ float xs[8][Fin];

    const int tx = threadIdx.x;
    const int b0 = blockIdx.x * 8;

    for (int idx = tx; idx < 8 * Hdim; idx += 256) {
        int r = idx >> 8, k = idx & 255;
        hf[r][k] = g_hfinal[(size_t)(b0 + r) * Hdim + k];
    }
    if (tx < 64) {
        int r = tx >> 3, cc = tx & 7;
        xs[r][cc] = x[(size_t)(b0 + r) * (Wlen * Fin) + (Wlen - 1) * Fin + cc];
    }
    __syncthreads();

    {   // backward cell at h0 = 0
        const int j = tx;
        float wr[Fin], wz[Fin], wn[Fin];
#pragma unroll
        for (int cc = 0; cc < Fin; cc++) {
            wr[cc] = Wih_b[j * Fin + cc];
            wz[cc] = Wih_b[(256 + j) * Fin + cc];
            wn[cc] = Wih_b[(512 + j) * Fin + cc];
        }
        const float bir = bih_b[j],       bhr = bhh_b[j];
        const float biz = bih_b[256 + j], bhz = bhh_b[256 + j];
        const float bin = bih_b[512 + j], bhn = bhh_b[512 + j];
#pragma unroll
        for (int r8 = 0; r8 < 8; r8++) {
            float gr = bir + bhr, gz = biz + bhz, gn = bin;
#pragma unroll
            for (int cc = 0; cc < Fin; cc++) {
                float xvv = xs[r8][cc];
                gr = fmaf(xvv, wr[cc], gr);
                gz = fmaf(xvv, wz[cc], gz);
                gn = fmaf(xvv, wn[cc], gn);
            }
            float r = 1.0f / (1.0f + __expf(-gr));
            float z = 1.0f / (1.0f + __expf(-gz));
            float an = gn + r * bhn;
            an = fminf(fmaxf(an, -15.0f), 15.0f);
            float e = __expf(-2.0f * an);
            float n = (1.0f - e) / (1.0f + e);
            hb[r8][j] = (1.0f - z) * n;
        }
    }
    __syncthreads();

    {   // projection + exact GELU
        const int j = tx;
#pragma unroll
        for (int r8 = 0; r8 < 8; r8++) {
            float acc = bp[j];
#pragma unroll 4
            for (int k = 0; k < Hdim; k++)
                acc = fmaf(hf[r8][k], g_Wpt[k * Hdim + j], acc);
#pragma unroll 4
            for (int k = 0; k < Hdim; k++)
                acc = fmaf(hb[r8][k], g_Wpt[(Hdim + k) * Hdim + j], acc);
            ys[r8][j] = 0.5f * acc * (1.0f + erff(acc * 0.70710678118654752f));
        }
    }
    __syncthreads();

    const int w = tx >> 5, l = tx & 31;
    float s1 = 0.f, s2 = 0.f;
#pragma unroll
    for (int m = 0; m < 8; m++) {
        float v = ys[w][l + 32 * m];
        s1 += v; s2 += v * v;
    }
#pragma unroll
    for (int o = 16; o > 0; o >>= 1) {
        s1 += __shfl_xor_sync(0xffffffffu, s1, o);
        s2 += __shfl_xor_sync(0xffffffffu, s2, o);
    }
    const float mu  = s1 * (1.0f / 256.0f);
    const float var = s2 * (1.0f / 256.0f) - mu * mu;
    const float inv = rsqrtf(var + 1e-5f);
#pragma unroll
    for (int m = 0; m < 8; m++) {
        int col = l + 32 * m;
        float v = (ys[w][col] - mu) * inv;
        out[(size_t)(b0 + w) * Hdim + col] = v * gamma[col] + beta[col];
    }
}

// ---------------------------------------------------------------------------
extern "C" void kernel_launch(void* const* d_in, const int* in_sizes, int n_in,
                              void* d_out, int out_size) {
    const float* x     = (const float*)d_in[0];
    const float* Wih_f = (const float*)d_in[1];
    const float* Whh_f = (const float*)d_in[2];
    const float* bih_f = (const float*)d_in[3];
    const float* bhh_f = (const float*)d_in[4];
    const float* Wih_b = (const float*)d_in[5];
    /* Whh_b = d_in[6] unused: backward cell has h0 = 0 */
    const float* bih_b = (const float*)d_in[7];
    const float* bhh_b = (const float*)d_in[8];
    const float* Wp    = (const float*)d_in[9];
    const float* bp    = (const float*)d_in[10];
    const float* gamma = (const float*)d_in[11];
    const float* beta  = (const float*)d_in[12];
    float* out = (float*)d_out;

    cudaFuncSetAttribute(gru_persist<1>, cudaFuncAttributeMaxDynamicSharedMemorySize, SM_TOTAL);
    cudaFuncSetAttribute(gru_persist<2>, cudaFuncAttributeMaxDynamicSharedMemorySize, SM_TOTAL);

    // pick the 256-CTA variant only if the whole grid is guaranteed co-resident
    int dev = 0, sms = 0, nb = 0;
    cudaGetDevice(&dev);
    cudaDeviceGetAttribute(&sms, cudaDevAttrMultiProcessorCount, dev);
    cudaOccupancyMaxActiveBlocksPerMultiprocessor(&nb, gru_persist<1>, 256, SM_TOTAL);

    prep_kernel<<<(N_PREP + 255) / 256, 256>>>(Whh_f, Wih_f, bih_f, bhh_f, Wp);

    if ((long)nb * sms >= 256)
        gru_persist<1><<<256, 256, SM_TOTAL>>>(x);
    else
        gru_persist<2><<<128, 256, SM_TOTAL>>>(x);

    head_kernel<<<Bsz / 8, 256>>>(x, Wih_b, bih_b, bhh_b, bp, gamma, beta, out);
}

// round 7
// speedup vs baseline: 3.3714x; 1.0471x over previous
#include <cuda_runtime.h>
#include <cuda_bf16.h>
#include <math.h>

// StatEncoder — persistent mma.sync (bf16 HMMA) GRU, plain sm_100 target.
//   256 CTAs (M=64, 2/SM) via MPW=1; MPW=2 (128 CTAs) fallback.
//   D[M,96] = A[M,256] @ W^T, m16n8k16 bf16, 3 passes (hi*Whi, hi*Wlo,
//   lo*Whi) => ~fp32 recurrence precision.
//   NEW: no step barrier. Per-warp producer flags (red.release.add by all
//   lanes / ld.acquire poll); dependency closure is 16 warps (same bt, wr).
//   q-loop starts at the warp's OWN chunk (A-frag kept in registers from the
//   epilogue), remaining chunks poll+load software-pipelined one ahead.
//   Epilogue h stores are 2x STG.128 (lane L owns words 4L..4L+3).

#define Bsz   2048
#define Wlen  128
#define Fin   8
#define Hdim  256

#define N_WF   196608          // 8c x 2p x 16q x 12nf x 32L x 2w words
#define N_WX   6144
#define N_HZ   524288          // parity-0 A planes
#define N_WPT  131072
#define NFLAG  2048            // [bt(32)][c(8)][wr(4)][wc(2)]

// dynamic smem layout (bytes)
#define SM_WX     98304
#define SM_BIAS   101376
#define SM_TOTAL  105472

// ---- static device scratch ----
__device__ __align__(256) unsigned g_wfrag[N_WF];
__device__ __align__(256) float    g_wx[N_WX];
__device__ __align__(256) float    g_bias[1024];      // cb_r | cb_z | bhn | bin
// [par][pl][rb(128)][q(16)][128 words]
__device__ __align__(256) unsigned g_hA[2 * 2 * 128 * 16 * 128];
__device__ __align__(256) float    g_hfinal[Bsz * Hdim];
__device__ __align__(256) float    g_Wpt[N_WPT];
__device__ int g_flag[NFLAG];

// ---- helpers ----
static __device__ __forceinline__ unsigned f2bf_bits(float f) {
    __nv_bfloat16 h = __float2bfloat16_rn(f);
    return (unsigned)reinterpret_cast<unsigned short&>(h);
}
static __device__ __forceinline__ float bfbits2f(unsigned u) {
    unsigned short us = (unsigned short)u;
    __nv_bfloat16 h = reinterpret_cast<__nv_bfloat16&>(us);
    return __bfloat162float(h);
}
static __device__ __forceinline__ unsigned ld_acq(const int* p) {
    unsigned v;
    asm volatile("ld.acquire.gpu.global.u32 %0, [%1];" : "=r"(v) : "l"(p) : "memory");
    return v;
}
static __device__ __forceinline__ void red_rel_add(int* p, unsigned v) {
    asm volatile("red.release.gpu.global.add.u32 [%0], %1;" :: "l"(p), "r"(v) : "memory");
}

#define MMA4(d, a, b0v, b1v)                                                   \
    asm volatile(                                                              \
        "mma.sync.aligned.m16n8k16.row.col.f32.bf16.bf16.f32 "                 \
        "{%0,%1,%2,%3}, {%4,%5,%6,%7}, {%8,%9}, {%0,%1,%2,%3};"                \
        : "+f"(d[0]), "+f"(d[1]), "+f"(d[2]), "+f"(d[3])                       \
        : "r"(a.x), "r"(a.y), "r"(a.z), "r"(a.w), "r"(b0v), "r"(b1v))

// ---------------- prep ------------------------------------------------------
#define N_PREP (N_WF + N_WX + 256 + N_HZ + NFLAG + N_WPT)

__global__ void prep_kernel(const float* __restrict__ Whh_f,
                            const float* __restrict__ Wih_f,
                            const float* __restrict__ bih_f,
                            const float* __restrict__ bhh_f,
                            const float* __restrict__ Wp) {
    int idx = blockIdx.x * blockDim.x + threadIdx.x;
    if (idx < N_WF) {
        int c  = idx / 24576, r = idx % 24576;
        int p  = r / 12288,  r2 = r % 12288;
        int q  = r2 / 768,   r3 = r2 % 768;
        int nfg = r3 / 64,   r4 = r3 % 64;
        int L  = r4 >> 1,    ws = r4 & 1;
        int n  = nfg * 8 + (L >> 2);
        int wc = n / 48, r5 = n % 48;
        int gate = r5 / 16;                 // 0=r, 1=z, 2=hn
        int jl = wc * 16 + (r5 % 16);
        int j  = c * 32 + jl;
        int k0 = q * 16 + ((L & 3) << 1) + ws * 8;
        float v0 = Whh_f[(gate * 256 + j) * 256 + k0];
        float v1 = Whh_f[(gate * 256 + j) * 256 + k0 + 1];
        unsigned w0, w1;
        if (p == 0) { w0 = f2bf_bits(v0); w1 = f2bf_bits(v1); }
        else {
            unsigned h0 = f2bf_bits(v0), h1 = f2bf_bits(v1);
            w0 = f2bf_bits(v0 - bfbits2f(h0));
            w1 = f2bf_bits(v1 - bfbits2f(h1));
        }
        g_wfrag[idx] = w0 | (w1 << 16);
    } else if (idx < N_WF + N_WX) {
        int i = idx - N_WF;
        int c = i / 768, r = i % 768;
        int jl = r / 24, g = (r % 24) / 8, e = r % 8;
        int j = c * 32 + jl;
        g_wx[i] = Wih_f[(g * 256 + j) * 8 + e];    // g: 0=r, 1=z, 2=inn
    } else if (idx < N_WF + N_WX + 256) {
        int j = idx - N_WF - N_WX;
        g_bias[j]       = bih_f[j] + bhh_f[j];
        g_bias[256 + j] = bih_f[256 + j] + bhh_f[256 + j];
        g_bias[512 + j] = bhh_f[512 + j];
        g_bias[768 + j] = bih_f[512 + j];
    } else if (idx < N_WF + N_WX + 256 + N_HZ) {
        g_hA[idx - N_WF - N_WX - 256] = 0u;        // parity-0 planes = h(0) = 0
    } else if (idx < N_WF + N_WX + 256 + N_HZ + NFLAG) {
        g_flag[idx - N_WF - N_WX - 256 - N_HZ] = 0;
    } else if (idx < N_PREP) {
        int i = idx - N_WF - N_WX - 256 - N_HZ - NFLAG;
        int m = i / Hdim, j = i - m * Hdim;
        g_Wpt[i] = Wp[j * (2 * Hdim) + m];
    }
}

// ---------------- persistent GRU -------------------------------------------
template<int MPW>
__global__ void __launch_bounds__(256, 2)
gru_persist(const float* __restrict__ x) {
    extern __shared__ unsigned smem[];
    const int tid = threadIdx.x;
    const int bt = blockIdx.x >> 3;     // batch-tile group
    const int c  = blockIdx.x & 7;      // column group 0..7

    // resident weights / wx / bias
    {
        const uint4* src = (const uint4*)(g_wfrag + c * 24576);
        uint4* dst = (uint4*)smem;
        for (int i = tid; i < 6144; i += 256) dst[i] = src[i];
        float* wxd = (float*)((char*)smem + SM_WX);
        const float* wxs = g_wx + c * 768;
        for (int i = tid; i < 768; i += 256) wxd[i] = wxs[i];
        float* bd = (float*)((char*)smem + SM_BIAS);
        for (int i = tid; i < 1024; i += 256) bd[i] = g_bias[i];
    }
    __syncthreads();

    const int w  = tid >> 5, L = tid & 31;
    const int wr = w >> 1;              // warp row-group
    const int wc = w & 1;               // N col half (16 jl)
    const unsigned* Wp0 = smem;                 // hi-plane B frags
    const unsigned* Wp1 = smem + 12288;         // lo-plane
    const float* swx = (const float*)((char*)smem + SM_WX);
    const float* sb  = (const float*)((char*)smem + SM_BIAS);
    const int qw   = 2 * c + wc;        // K-chunk this warp produces
    const int rbw  = bt * (4 * MPW) + wr * MPW; // first global row-block
    const int fbase = bt * 64 + wr * 2; // flag idx = fbase + c'*8 + wc'
    const int fown  = fbase + c * 8 + wc;

    float hold[MPW * 8];
#pragma unroll
    for (int i = 0; i < MPW * 8; i++) hold[i] = 0.0f;
    uint4 own_fa[MPW], own_fl[MPW];
#pragma unroll
    for (int m = 0; m < MPW; m++) {
        own_fa[m] = make_uint4(0u, 0u, 0u, 0u);
        own_fl[m] = make_uint4(0u, 0u, 0u, 0u);
    }

    for (int t = 0; t < Wlen; t++) {
        const int par = t & 1;
        const unsigned thr = 32u * (unsigned)t;
        float acc[MPW][6][4];
#pragma unroll
        for (int m = 0; m < MPW; m++)
#pragma unroll
            for (int nf = 0; nf < 6; nf++)
#pragma unroll
                for (int u = 0; u < 4; u++) acc[m][nf][u] = 0.0f;

        // x(t) prefetch (independent of h)
        float4 xv[MPW * 2][2];
#pragma unroll
        for (int m = 0; m < MPW; m++)
#pragma unroll
            for (int rh = 0; rh < 2; rh++) {
                const int row = (rbw + m) * 16 + (L >> 2) + 8 * rh;
                const float4* xp = (const float4*)(x + (size_t)row * (Wlen * Fin) + t * Fin);
                xv[m * 2 + rh][0] = __ldg(xp);
                xv[m * 2 + rh][1] = __ldg(xp + 1);
            }

        const unsigned* Ah = g_hA + ((size_t)(par * 2 + 0) * 128 + rbw) * 2048;
        const unsigned* Al = g_hA + ((size_t)(par * 2 + 1) * 128 + rbw) * 2048;

        // chunk 0 = own chunk, fragments already in registers
        uint4 cfa[MPW], cfl[MPW];
#pragma unroll
        for (int m = 0; m < MPW; m++) { cfa[m] = own_fa[m]; cfl[m] = own_fl[m]; }

        // pre-issue poll for the next chunk
        int qn0 = (qw + 1) & 15;
        unsigned fv = ld_acq(&g_flag[fbase + (qn0 >> 1) * 8 + (qn0 & 1)]);

#pragma unroll 2
        for (int qq = 0; qq < 16; qq++) {
            const int q = (qw + qq) & 15;
            uint4 nfa[MPW], nfl[MPW];
            if (qq < 15) {
                const int qn = (qw + qq + 1) & 15;
                const int fidx = fbase + (qn >> 1) * 8 + (qn & 1);
                long guard = 0;
                while (fv < thr && guard < 1000000000L) { fv = ld_acq(&g_flag[fidx]); guard++; }
#pragma unroll
                for (int m = 0; m < MPW; m++) {
                    nfa[m] = __ldcg((const uint4*)(Ah + (size_t)m * 2048 + qn * 128) + L);
                    nfl[m] = __ldcg((const uint4*)(Al + (size_t)m * 2048 + qn * 128) + L);
                }
                if (qq < 14) {
                    const int qn2 = (qw + qq + 2) & 15;
                    fv = ld_acq(&g_flag[fbase + (qn2 >> 1) * 8 + (qn2 & 1)]);
                }
            }
            unsigned bh[6][2];
            const int bbase = (q * 12 + wc * 6) * 64 + (L << 1);
#pragma unroll
            for (int nf = 0; nf < 6; nf++) {          // pass 1: A_hi * W_hi
                uint2 bb = *(const uint2*)(Wp0 + bbase + nf * 64);
                bh[nf][0] = bb.x; bh[nf][1] = bb.y;
#pragma unroll
                for (int m = 0; m < MPW; m++) MMA4(acc[m][nf], cfa[m], bb.x, bb.y);
            }
#pragma unroll
            for (int nf = 0; nf < 6; nf++) {          // pass 2: A_hi * W_lo
                uint2 bb = *(const uint2*)(Wp1 + bbase + nf * 64);
#pragma unroll
                for (int m = 0; m < MPW; m++) MMA4(acc[m][nf], cfa[m], bb.x, bb.y);
            }
#pragma unroll
            for (int nf = 0; nf < 6; nf++)            // pass 3: A_lo * W_hi
#pragma unroll
                for (int m = 0; m < MPW; m++) MMA4(acc[m][nf], cfl[m], bh[nf][0], bh[nf][1]);
#pragma unroll
            for (int m = 0; m < MPW; m++) { cfa[m] = nfa[m]; cfl[m] = nfl[m]; }
        }

        // ---- epilogue: x-proj (fp32) + gates + h update + frag store -------
        const int pw = par ^ 1;
#pragma unroll
        for (int m = 0; m < MPW; m++) {
            const int rb = rbw + m;
            unsigned whi[4], wlo[4];
#pragma unroll
            for (int rh = 0; rh < 2; rh++) {
                const float x8[8] = {xv[m * 2 + rh][0].x, xv[m * 2 + rh][0].y,
                                     xv[m * 2 + rh][0].z, xv[m * 2 + rh][0].w,
                                     xv[m * 2 + rh][1].x, xv[m * 2 + rh][1].y,
                                     xv[m * 2 + rh][1].z, xv[m * 2 + rh][1].w};
#pragma unroll
                for (int fp = 0; fp < 2; fp++) {
                    float hpair[2];
#pragma unroll
                    for (int e = 0; e < 2; e++) {
                        const int jl = wc * 16 + 2 * (L & 3) + 8 * fp + e;
                        const int j  = c * 32 + jl;
                        const float* wj = swx + jl * 24;
                        float xr = 0.f, xz = 0.f, xn = 0.f;
#pragma unroll
                        for (int u = 0; u < 8; u++) {
                            xr = fmaf(x8[u], wj[u], xr);
                            xz = fmaf(x8[u], wj[8 + u], xz);
                            xn = fmaf(x8[u], wj[16 + u], xn);
                        }
                        const int ci = rh * 2 + e;
                        float rp   = acc[m][fp][ci]     + xr + sb[j];
                        float zp   = acc[m][2 + fp][ci] + xz + sb[256 + j];
                        float hnv  = acc[m][4 + fp][ci] + sb[512 + j];
                        float innv = xn + sb[768 + j];
                        float r = __fdividef(1.0f, 1.0f + __expf(-rp));
                        float z = __fdividef(1.0f, 1.0f + __expf(-zp));
                        float an = innv + r * hnv;
                        an = fminf(fmaxf(an, -15.0f), 15.0f);
                        float e2 = __expf(-2.0f * an);
                        float n  = (1.0f - e2) * __fdividef(1.0f, 1.0f + e2);
                        const int hidx = ((m * 2 + rh) * 2 + fp) * 2 + e;
                        float h = (1.0f - z) * n + z * hold[hidx];
                        hold[hidx] = h;
                        hpair[e] = h;
                    }
                    unsigned hb0 = f2bf_bits(hpair[0]);
                    unsigned hb1 = f2bf_bits(hpair[1]);
                    unsigned lb0 = f2bf_bits(hpair[0] - bfbits2f(hb0));
                    unsigned lb1 = f2bf_bits(hpair[1] - bfbits2f(hb1));
                    whi[rh + 2 * fp] = hb0 | (hb1 << 16);
                    wlo[rh + 2 * fp] = lb0 | (lb1 << 16);
                }
            }
            own_fa[m] = make_uint4(whi[0], whi[1], whi[2], whi[3]);
            own_fl[m] = make_uint4(wlo[0], wlo[1], wlo[2], wlo[3]);
            *(((uint4*)(g_hA + ((size_t)(pw * 2 + 0) * 128 + rb) * 2048 + qw * 128)) + L) = own_fa[m];
            *(((uint4*)(g_hA + ((size_t)(pw * 2 + 1) * 128 + rb) * 2048 + qw * 128)) + L) = own_fl[m];
        }
        // release: each lane's red.release orders its own prior stores
        red_rel_add(&g_flag[fown], 1u);
    }

    // final h -> plain layout for the head
#pragma unroll
    for (int m = 0; m < MPW; m++)
#pragma unroll
        for (int rh = 0; rh < 2; rh++) {
            const int row = (rbw + m) * 16 + (L >> 2) + 8 * rh;
#pragma unroll
            for (int fp = 0; fp < 2; fp++)
#pragma unroll
                for (int e = 0; e < 2; e++) {
                    const int jl = wc * 16 + 2 * (L & 3) + 8 * fp + e;
                    const int hidx = ((m * 2 + rh) * 2 + fp) * 2 + e;
                    g_hfinal[(size_t)row * 256 + c * 32 + jl] = hold[hidx];
                }
        }
}

// ---------------- head: h_bwd + projection + GELU + LayerNorm ---------------
__global__ void __launch_bounds__(256)
head_kernel(const float* __restrict__ x,
            const float* __restrict__ Wih_b,
            const float* __restrict__ bih_b,
            const float* __restrict__ bhh_b,
            const float* __restrict__ bp,
            const float* __restrict__ gamma,
            const float* __restrict__ beta,
            float* __restrict__ out) {
    __shared__ float hf[8][Hdim];
    __shared__ float hb[8][Hdim];
    __shared__ float ys[8][Hdim];
    __shared__ float xs[8][Fin];

    const int tx = threadIdx.x;
    const int b0 = blockIdx.x * 8;

    for (int idx = tx; idx < 8 * Hdim; idx += 256) {
        int r = idx >> 8, k = idx & 255;
        hf[r][k] = g_hfinal[(size_t)(b0 + r) * Hdim + k];
    }
    if (tx < 64) {
        int r = tx >> 3, cc = tx & 7;
        xs[r][cc] = x[(size_t)(b0 + r) * (Wlen * Fin) + (Wlen - 1) * Fin + cc];
    }
    __syncthreads();

    {   // backward cell at h0 = 0
        const int j = tx;
        float wr[Fin], wz[Fin], wn[Fin];
#pragma unroll
        for (int cc = 0; cc < Fin; cc++) {
            wr[cc] = Wih_b[j * Fin + cc];
            wz[cc] = Wih_b[(256 + j) * Fin + cc];
            wn[cc] = Wih_b[(512 + j) * Fin + cc];
        }
        const float bir = bih_b[j],       bhr = bhh_b[j];
        const float biz = bih_b[256 + j], bhz = bhh_b[256 + j];
        const float bin = bih_b[512 + j], bhn = bhh_b[512 + j];
#pragma unroll
        for (int r8 = 0; r8 < 8; r8++) {
            float gr = bir + bhr, gz = biz + bhz, gn = bin;
#pragma unroll
            for (int cc = 0; cc < Fin; cc++) {
                float xvv = xs[r8][cc];
                gr = fmaf(xvv, wr[cc], gr);
                gz = fmaf(xvv, wz[cc], gz);
                gn = fmaf(xvv, wn[cc], gn);
            }
            float r = 1.0f / (1.0f + __expf(-gr));
            float z = 1.0f / (1.0f + __expf(-gz));
            float an = gn + r * bhn;
            an = fminf(fmaxf(an, -15.0f), 15.0f);
            float e = __expf(-2.0f * an);
            float n = (1.0f - e) / (1.0f + e);
            hb[r8][j] = (1.0f - z) * n;
        }
    }
    __syncthreads();

    {   // projection + exact GELU
        const int j = tx;
#pragma unroll
        for (int r8 = 0; r8 < 8; r8++) {
            float acc = bp[j];
#pragma unroll 4
            for (int k = 0; k < Hdim; k++)
                acc = fmaf(hf[r8][k], g_Wpt[k * Hdim + j], acc);
#pragma unroll 4
            for (int k = 0; k < Hdim; k++)
                acc = fmaf(hb[r8][k], g_Wpt[(Hdim + k) * Hdim + j], acc);
            ys[r8][j] = 0.5f * acc * (1.0f + erff(acc * 0.70710678118654752f));
        }
    }
    __syncthreads();

    const int w = tx >> 5, l = tx & 31;
    float s1 = 0.f, s2 = 0.f;
#pragma unroll
    for (int m = 0; m < 8; m++) {
        float v = ys[w][l + 32 * m];
        s1 += v; s2 += v * v;
    }
#pragma unroll
    for (int o = 16; o > 0; o >>= 1) {
        s1 += __shfl_xor_sync(0xffffffffu, s1, o);
        s2 += __shfl_xor_sync(0xffffffffu, s2, o);
    }
    const float mu  = s1 * (1.0f / 256.0f);
    const float var = s2 * (1.0f / 256.0f) - mu * mu;
    const float inv = rsqrtf(var + 1e-5f);
#pragma unroll
    for (int m = 0; m < 8; m++) {
        int col = l + 32 * m;
        float v = (ys[w][col] - mu) * inv;
        out[(size_t)(b0 + w) * Hdim + col] = v * gamma[col] + beta[col];
    }
}

// ---------------------------------------------------------------------------
extern "C" void kernel_launch(void* const* d_in, const int* in_sizes, int n_in,
                              void* d_out, int out_size) {
    const float* x     = (const float*)d_in[0];
    const float* Wih_f = (const float*)d_in[1];
    const float* Whh_f = (const float*)d_in[2];
    const float* bih_f = (const float*)d_in[3];
    const float* bhh_f = (const float*)d_in[4];
    const float* Wih_b = (const float*)d_in[5];
    /* Whh_b = d_in[6] unused: backward cell has h0 = 0 */
    const float* bih_b = (const float*)d_in[7];
    const float* bhh_b = (const float*)d_in[8];
    const float* Wp    = (const float*)d_in[9];
    const float* bp    = (const float*)d_in[10];
    const float* gamma = (const float*)d_in[11];
    const float* beta  = (const float*)d_in[12];
    float* out = (float*)d_out;

    cudaFuncSetAttribute(gru_persist<1>, cudaFuncAttributeMaxDynamicSharedMemorySize, SM_TOTAL);
    cudaFuncSetAttribute(gru_persist<2>, cudaFuncAttributeMaxDynamicSharedMemorySize, SM_TOTAL);

    int dev = 0, sms = 0, nb = 0;
    cudaGetDevice(&dev);
    cudaDeviceGetAttribute(&sms, cudaDevAttrMultiProcessorCount, dev);
    cudaOccupancyMaxActiveBlocksPerMultiprocessor(&nb, gru_persist<1>, 256, SM_TOTAL);

    prep_kernel<<<(N_PREP + 255) / 256, 256>>>(Whh_f, Wih_f, bih_f, bhh_f, Wp);

    if ((long)nb * sms >= 256)
        gru_persist<1><<<256, 256, SM_TOTAL>>>(x);
    else
        gru_persist<2><<<128, 256, SM_TOTAL>>>(x);

    head_kernel<<<Bsz / 8, 256>>>(x, Wih_b, bih_b, bhh_b, bp, gamma, beta, out);
}